// round 17
// baseline (speedup 1.0000x reference)
#include <cuda_runtime.h>
#include <math.h>
#include <stdint.h>

// ---------------- problem constants (fixed shapes) ----------------
#define N_NODES 131072
#define EDIM    64
#define L0      262144
#define L1      524288
#define L2      393216
#define NROWS   (L0 + L1 + L2)   // 1179648
#define SCAN_BLOCKS 512          // N_NODES / 256

// ---------------- scratch (device globals; no cudaMalloc allowed) ----------
__device__ float g_msg[(size_t)NROWS * EDIM];     // node-sorted message rows
__device__ float g_mf [(size_t)N_NODES * EDIM];   // final max_msg per node
__device__ int   g_idx[NROWS];
__device__ int   g_cnt[N_NODES];                  // zero at load; reduce re-zeroes
__device__ int   g_start[N_NODES];
__device__ int   g_rank[N_NODES];                 // zeroed by scanBC each run
__device__ int   g_flag[N_NODES];                 // zero at load; reduce re-zeroes
__device__ int   g_bsum[SCAN_BLOCKS];

// ---------------- helpers ----------------
__device__ __forceinline__ float mishf(float x) {
    float sp = (x > 20.0f) ? x : log1pf(expf(x));
    return x * tanhf(sp);
}

// ---- packed f32x2 FMA (ptxas never emits FFMA2 from C++; PTX-only) ----
typedef unsigned long long ull;
__device__ __forceinline__ ull dup2(float w) {
    ull d;
    asm("mov.b64 %0, {%1, %1};" : "=l"(d) : "f"(w));
    return d;
}
__device__ __forceinline__ void fma2(ull& acc, ull x, ull w) {
    asm("fma.rn.f32x2 %0, %1, %2, %3;" : "=l"(acc) : "l"(x), "l"(w), "l"(acc));
}
__device__ __forceinline__ void unpack2(ull v, float& lo, float& hi) {
    asm("mov.b64 {%0, %1}, %2;" : "=f"(lo), "=f"(hi) : "l"(v));
}

// ---------------- 1. convert + histogram + rel0 flag (inline dtype detect) -
__global__ void convhist_kernel(const void* __restrict__ p0,
                                const void* __restrict__ p1,
                                const void* __restrict__ p2) {
    __shared__ int modeS;
    if (threadIdx.x < 32) {
        unsigned v = 0;
        if (threadIdx.x < 16) v = ((const unsigned*)p0)[threadIdx.x * 2 + 1];
        unsigned any = __ballot_sync(0xffffffffu, v != 0);
        if (threadIdx.x == 0) modeS = any ? 1 : 0;   // 1 = int32 data
    }
    __syncthreads();
    const int mode = modeS;

    int i = blockIdx.x * 256 + threadIdx.x;
    if (i >= NROWS) return;
    const void* p; int o;
    if      (i < L0)      { p = p0; o = i; }
    else if (i < L0 + L1) { p = p1; o = i - L0; }
    else                  { p = p2; o = i - L0 - L1; }
    int v;
    if (mode) v = ((const int*)p)[o];
    else      v = (int)(((const long long*)p)[o]);
    g_idx[i] = v;
    atomicAdd(&g_cnt[v], 1);
    if (i < L0) g_flag[v] = 1;   // racy identical writes: benign
}

// ---------------- 2a. per-block (256 nodes) sums ----------------
__global__ void scanA_kernel() {
    __shared__ int wsum[8];
    const int t = threadIdx.x;
    int v = g_cnt[blockIdx.x * 256 + t];
#pragma unroll
    for (int s = 16; s > 0; s >>= 1) v += __shfl_down_sync(0xffffffffu, v, s);
    if ((t & 31) == 0) wsum[t >> 5] = v;
    __syncthreads();
    if (t < 8) {
        int x = wsum[t];
#pragma unroll
        for (int s = 4; s > 0; s >>= 1) x += __shfl_down_sync(0xffu, x, s);
        if (t == 0) g_bsum[blockIdx.x] = x;
    }
}

// ---------------- 2b. base offset (masked reduce) + local scan --------------
__global__ void scanBC_kernel() {
    __shared__ int wsum[8];
    __shared__ int baseS;
    const int t = threadIdx.x;
    const int lane = t & 31, w = t >> 5;
    const int b = blockIdx.x;

    {
        int j0 = 2 * t, j1 = 2 * t + 1;
        int v = ((j0 < b) ? g_bsum[j0] : 0) + ((j1 < b) ? g_bsum[j1] : 0);
#pragma unroll
        for (int s = 16; s > 0; s >>= 1) v += __shfl_down_sync(0xffffffffu, v, s);
        if (lane == 0) wsum[w] = v;
        __syncthreads();
        if (t < 8) {
            int x = wsum[t];
#pragma unroll
            for (int s = 4; s > 0; s >>= 1) x += __shfl_down_sync(0xffu, x, s);
            if (t == 0) baseS = x;
        }
        __syncthreads();
    }

    const int i = b * 256 + t;
    int v = g_cnt[i];
    int inc = v;
#pragma unroll
    for (int s = 1; s < 32; s <<= 1) {
        int u = __shfl_up_sync(0xffffffffu, inc, s);
        if (lane >= s) inc += u;
    }
    __syncthreads();
    if (lane == 31) wsum[w] = inc;
    __syncthreads();
    if (t < 8) {
        int x = wsum[t];
#pragma unroll
        for (int s = 1; s < 8; s <<= 1) {
            int u = __shfl_up_sync(0xffu, x, s);
            if (t >= s) x += u;
        }
        wsum[t] = x;
    }
    __syncthreads();
    int wofs = (w == 0) ? 0 : wsum[w - 1];
    g_start[i] = baseS + wofs + inc - v;
    g_rank[i]  = 0;
}

// ---------------- 3. per-relation fused gather + MLP + sorted store --------
// Warp-aligned tiles: 4 warps per 128-thread block, ONE tile (8 tuples) per
// warp -> the x-pair LDS.128 is a true warp broadcast for every D.
// Each thread owns CPT = D/32 adjacent columns as G = CPT/2 float2-groups.
// Row pairs packed in f32x2 lanes: xs[tile][p][2k+h] = elem k of rows
// (2p, 2p+1). z overwrites xs in place after a barrier.
template <int D, int A, int MAXB>
__global__ void __launch_bounds__(128, MAXB)
msg_kernel(const float* __restrict__ emb,
           const float* __restrict__ rw, const float* __restrict__ rb,
           const float* __restrict__ ow, const float* __restrict__ ob,
           int idx_ofs) {
    constexpr int R2  = 4;              // row pairs per tile (8 tuples)
    constexpr int CPT = D / 32;         // columns per thread
    constexpr int G   = CPT / 2;        // float2 column groups
    __shared__ __align__(16) float xs[4][R2][2 * D];   // x, then z in-place
    __shared__ int idxS[32 * A];
    __shared__ int posS[32 * A];
    const int tid   = threadIdx.x;
    const int tile  = tid >> 5;          // warp id = tile id
    const int c     = tid & 31;
    const int col   = c * CPT;           // first owned column
    const int t0    = blockIdx.x * 32;
    const int rbase = tile * 8;          // tuple base within block

    // one thread per message row: node + fused rank (segment order arbitrary)
    if (tid < 32 * A) {
        int node = g_idx[idx_ofs + t0 * A + tid];
        idxS[tid] = node;
        posS[tid] = g_start[node] + atomicAdd(&g_rank[node], 1);
    }
    __syncthreads();

    // gather row pairs into this tile's smem slice, group by group
#pragma unroll
    for (int p = 0; p < R2; ++p) {
#pragma unroll
        for (int g = 0; g < G; ++g) {
            int cg = col + 2 * g;
            int jg = cg >> 6;
            int eg = cg & 63;
            int n0 = idxS[(rbase + 2 * p) * A + jg];
            int n1 = idxS[(rbase + 2 * p + 1) * A + jg];
            float2 a = *(const float2*)&emb[(size_t)n0 * EDIM + eg];
            float2 b = *(const float2*)&emb[(size_t)n1 * EDIM + eg];
            *(float4*)&xs[tile][p][2 * cg] = make_float4(a.x, b.x, a.y, b.y);
        }
    }
    __syncthreads();

    ull acc[2 * G][R2];   // [packed col][row pair], rows packed in f32x2
    // ---- h = x @ rw + rb ----
#pragma unroll
    for (int g = 0; g < G; ++g) {
        float2 b = *(const float2*)&rb[col + 2 * g];
#pragma unroll
        for (int p = 0; p < R2; ++p) {
            acc[2 * g][p] = dup2(b.x); acc[2 * g + 1][p] = dup2(b.y);
        }
    }
#pragma unroll 2
    for (int k = 0; k < D; k += 2) {
#pragma unroll
        for (int g = 0; g < G; ++g) {
            float2 w0 = *(const float2*)&rw[(k + 0) * D + col + 2 * g];
            float2 w1 = *(const float2*)&rw[(k + 1) * D + col + 2 * g];
            ull Wa = dup2(w0.x), Wb = dup2(w0.y);
            ull Wc = dup2(w1.x), Wd = dup2(w1.y);
#pragma unroll
            for (int p = 0; p < R2; ++p) {
                ulonglong2 x2 = *(const ulonglong2*)&xs[tile][p][2 * k];
                fma2(acc[2 * g][p],     x2.x, Wa);
                fma2(acc[2 * g + 1][p], x2.x, Wb);
                fma2(acc[2 * g][p],     x2.y, Wc);
                fma2(acc[2 * g + 1][p], x2.y, Wd);
            }
        }
    }
    __syncthreads();   // all GEMM1 reads of xs complete before overwrite

    // ---- z = x + mish(h), written in place over xs ----
#pragma unroll
    for (int p = 0; p < R2; ++p) {
#pragma unroll
        for (int g = 0; g < G; ++g) {
            int cg = col + 2 * g;
            float hA0, hA1, hB0, hB1;
            unpack2(acc[2 * g][p],     hA0, hA1);   // col cg: rows (2p, 2p+1)
            unpack2(acc[2 * g + 1][p], hB0, hB1);   // col cg+1
            float4 xv = *(const float4*)&xs[tile][p][2 * cg];
            xv.x += mishf(hA0); xv.y += mishf(hA1);
            xv.z += mishf(hB0); xv.w += mishf(hB1);
            *(float4*)&xs[tile][p][2 * cg] = xv;
        }
    }
    __syncthreads();

    // ---- out = z @ ow + ob ----
#pragma unroll
    for (int g = 0; g < G; ++g) {
        float2 b = *(const float2*)&ob[col + 2 * g];
#pragma unroll
        for (int p = 0; p < R2; ++p) {
            acc[2 * g][p] = dup2(b.x); acc[2 * g + 1][p] = dup2(b.y);
        }
    }
#pragma unroll 2
    for (int k = 0; k < D; k += 2) {
#pragma unroll
        for (int g = 0; g < G; ++g) {
            float2 w0 = *(const float2*)&ow[(k + 0) * D + col + 2 * g];
            float2 w1 = *(const float2*)&ow[(k + 1) * D + col + 2 * g];
            ull Wa = dup2(w0.x), Wb = dup2(w0.y);
            ull Wc = dup2(w1.x), Wd = dup2(w1.y);
#pragma unroll
            for (int p = 0; p < R2; ++p) {
                ulonglong2 z2 = *(const ulonglong2*)&xs[tile][p][2 * k];
                fma2(acc[2 * g][p],     z2.x, Wa);
                fma2(acc[2 * g + 1][p], z2.x, Wb);
                fma2(acc[2 * g][p],     z2.y, Wc);
                fma2(acc[2 * g + 1][p], z2.y, Wd);
            }
        }
    }

    // ---- store message rows at node-sorted slots (pos from smem) ----
#pragma unroll
    for (int p = 0; p < R2; ++p) {
#pragma unroll
        for (int g = 0; g < G; ++g) {
            int cg = col + 2 * g;
            int jg = cg >> 6;
            int eg = cg & 63;
            float oA0, oA1, oB0, oB1;
            unpack2(acc[2 * g][p],     oA0, oA1);
            unpack2(acc[2 * g + 1][p], oB0, oB1);
            int p0 = posS[(rbase + 2 * p) * A + jg];
            int p1 = posS[(rbase + 2 * p + 1) * A + jg];
            *(float2*)&g_msg[(size_t)p0 * EDIM + eg] = make_float2(oA0, oB0);
            *(float2*)&g_msg[(size_t)p1 * EDIM + eg] = make_float2(oA1, oB1);
        }
    }
}

// ---------------- 4. segment softmax-reduce (online, 2-row unrolled) -------
__global__ void reduce_kernel() {
    int node = (blockIdx.x * blockDim.x + threadIdx.x) >> 5;
    if (node >= N_NODES) return;
    const int lane  = threadIdx.x & 31;
    const int start = g_start[node];
    const int end   = start + g_cnt[node];
    const float base = g_flag[node] ? -INFINITY : 0.0f;

    float m0 = base, m1 = base;
    float s0 = 0.0f, s1 = 0.0f;
    int r = start;
    for (; r + 2 <= end; r += 2) {
        const float* rowA = &g_msg[(size_t)r * EDIM];
        const float* rowB = &g_msg[(size_t)(r + 1) * EDIM];
        float a0 = rowA[lane], a1 = rowA[lane + 32];
        float b0 = rowB[lane], b1 = rowB[lane + 32];
        float n0 = fmaxf(m0, fmaxf(a0, b0));
        float n1 = fmaxf(m1, fmaxf(a1, b1));
        s0 = s0 * expf(12.0f * (m0 - n0)) + expf(12.0f * (a0 - n0))
                                          + expf(12.0f * (b0 - n0));
        s1 = s1 * expf(12.0f * (m1 - n1)) + expf(12.0f * (a1 - n1))
                                          + expf(12.0f * (b1 - n1));
        m0 = n0; m1 = n1;
    }
    if (r < end) {
        const float* row = &g_msg[(size_t)r * EDIM];
        float v0 = row[lane], v1 = row[lane + 32];
        float n0 = fmaxf(m0, v0), n1 = fmaxf(m1, v1);
        s0 = s0 * expf(12.0f * (m0 - n0)) + expf(12.0f * (v0 - n0));
        s1 = s1 * expf(12.0f * (m1 - n1)) + expf(12.0f * (v1 - n1));
        m0 = n0; m1 = n1;
    }
    s0 += 1e-16f; s1 += 1e-16f;
    size_t o = (size_t)node * EDIM;
    g_mf[o + lane]      = logf(s0) * (1.0f / 12.0f) + m0;
    g_mf[o + lane + 32] = logf(s1) * (1.0f / 12.0f) + m1;
    if (lane == 0) { g_cnt[node] = 0; g_flag[node] = 0; }   // ready for replay
}

// ---------------- 5. node update MLP (two-tile 2-col): [mf|emb](128)->64 ---
template <int R>
__global__ void __launch_bounds__(128, 8)
update_kernel(const float* __restrict__ emb,
              const float* __restrict__ rw, const float* __restrict__ rb,
              const float* __restrict__ ow, const float* __restrict__ ob,
              float* __restrict__ out) {
    constexpr int R2 = R / 2;
    __shared__ __align__(16) float xs[2][R2][256];   // x, then z in-place
    const int tid  = threadIdx.x;
    const int half = tid >> 6;          // which tile (2 warps per tile)
    const int c2   = tid & 63;
    const int col  = 2 * c2;            // 0..126, even
    const int n0g  = blockIdx.x * (2 * R) + half * R;

#pragma unroll
    for (int p = 0; p < R2; ++p) {
        int nA = n0g + 2 * p, nB = n0g + 2 * p + 1;
        float2 a, b;
        if (col < 64) {
            a = *(const float2*)&g_mf[(size_t)nA * EDIM + col];
            b = *(const float2*)&g_mf[(size_t)nB * EDIM + col];
        } else {
            a = *(const float2*)&emb[(size_t)nA * EDIM + (col - 64)];
            b = *(const float2*)&emb[(size_t)nB * EDIM + (col - 64)];
        }
        *(float4*)&xs[half][p][4 * c2] = make_float4(a.x, b.x, a.y, b.y);
    }
    __syncthreads();

    ull acc0[R2], acc1[R2];
    {
        float2 b = *(const float2*)&rb[col];
#pragma unroll
        for (int p = 0; p < R2; ++p) { acc0[p] = dup2(b.x); acc1[p] = dup2(b.y); }
    }
#pragma unroll 4
    for (int k = 0; k < 128; k += 2) {
        float2 wk0 = *(const float2*)&rw[(k + 0) * 128 + col];
        float2 wk1 = *(const float2*)&rw[(k + 1) * 128 + col];
        ull wA = dup2(wk0.x), wB = dup2(wk0.y);
        ull wC = dup2(wk1.x), wDd = dup2(wk1.y);
#pragma unroll
        for (int p = 0; p < R2; ++p) {
            ulonglong2 x2 = *(const ulonglong2*)&xs[half][p][2 * k];
            fma2(acc0[p], x2.x, wA);
            fma2(acc1[p], x2.x, wB);
            fma2(acc0[p], x2.y, wC);
            fma2(acc1[p], x2.y, wDd);
        }
    }
    __syncthreads();

#pragma unroll
    for (int p = 0; p < R2; ++p) {
        float h00, h01, h10, h11;
        unpack2(acc0[p], h00, h01);
        unpack2(acc1[p], h10, h11);
        float4 xv = *(const float4*)&xs[half][p][4 * c2];
        float4 v;
        v.x = xv.x + mishf(h00);
        v.y = xv.y + mishf(h01);
        v.z = xv.z + mishf(h10);
        v.w = xv.w + mishf(h11);
        *(float4*)&xs[half][p][4 * c2] = v;
    }
    __syncthreads();

    // ---- out = z @ ow + ob (N=64; one col per thread per tile) ----
    {
        ull a2[R2];
        float bc = ob[c2];
#pragma unroll
        for (int p = 0; p < R2; ++p) a2[p] = dup2(bc);
#pragma unroll 4
        for (int k = 0; k < 128; k += 2) {
            ull w0 = dup2(ow[(k + 0) * 64 + c2]);
            ull w1 = dup2(ow[(k + 1) * 64 + c2]);
#pragma unroll
            for (int p = 0; p < R2; ++p) {
                ulonglong2 z2 = *(const ulonglong2*)&xs[half][p][2 * k];
                fma2(a2[p], z2.x, w0);
                fma2(a2[p], z2.y, w1);
            }
        }
#pragma unroll
        for (int p = 0; p < R2; ++p) {
            float o0, o1;
            unpack2(a2[p], o0, o1);
            out[(size_t)(n0g + 2 * p + 0) * EDIM + c2] = o0;
            out[(size_t)(n0g + 2 * p + 1) * EDIM + c2] = o1;
        }
    }
}

// ---------------- launcher ----------------
extern "C" void kernel_launch(void* const* d_in, const int* in_sizes, int n_in,
                              void* d_out, int out_size) {
    const float* emb = (const float*)d_in[0];
    const void*  i0  = d_in[1];
    const void*  i1  = d_in[2];
    const void*  i2  = d_in[3];
    const float* r0rw = (const float*)d_in[4];
    const float* r0rb = (const float*)d_in[5];
    const float* r0ow = (const float*)d_in[6];
    const float* r0ob = (const float*)d_in[7];
    const float* r1rw = (const float*)d_in[8];
    const float* r1rb = (const float*)d_in[9];
    const float* r1ow = (const float*)d_in[10];
    const float* r1ob = (const float*)d_in[11];
    const float* r2rw = (const float*)d_in[12];
    const float* r2rb = (const float*)d_in[13];
    const float* r2ow = (const float*)d_in[14];
    const float* r2ob = (const float*)d_in[15];
    const float* urw  = (const float*)d_in[16];
    const float* urb  = (const float*)d_in[17];
    const float* uow  = (const float*)d_in[18];
    const float* uob  = (const float*)d_in[19];
    float* out = (float*)d_out;

    // prelude (3 launches)
    convhist_kernel<<<(NROWS + 255) / 256, 256>>>(i0, i1, i2);
    scanA_kernel<<<SCAN_BLOCKS, 256>>>();
    scanBC_kernel<<<SCAN_BLOCKS, 256>>>();

    // launch #4 = msg<128> (lands in the ncu capture window)
    // each block covers 32 tuples (4 warp-tiles x 8)
    msg_kernel<128, 2, 8><<<(L1 / 2) / 32, 128>>>(emb, r1rw, r1rb, r1ow, r1ob, L0);
    msg_kernel< 64, 1, 8><<<(L0 / 1) / 32, 128>>>(emb, r0rw, r0rb, r0ow, r0ob, 0);
    msg_kernel<192, 3, 6><<<(L2 / 3) / 32, 128>>>(emb, r2rw, r2rb, r2ow, r2ob, L0 + L1);

    // single-pass segment softmax-reduce, then node update (32 nodes/block)
    reduce_kernel<<<(N_NODES * 32 + 255) / 256, 256>>>();
    update_kernel<16><<<N_NODES / 32, 128>>>(emb, urw, urb, uow, uob, out);
}